// round 13
// baseline (speedup 1.0000x reference)
#include <cuda_runtime.h>

#define PI_F 3.14159265358979f
#define N1   512
#define N2   (512*512)
#define HH   256
#define WW   256
#define NA   5
#define NC   12
#define NIMG 60            // NC*NA

#define NX   (NA*HH*WW)    // 327680
#define NM   (NC*HH*WW)    // 786432
#define NK   (NA*NA*N2)    // 6553600
#define CAPG (NIMG*N2)     // scratch capacity in float2

// Scratch (static device globals: allocation-free, graph-safe). 2 x 126 MB.
__device__ float2 g_bufA[CAPG];
__device__ float2 g_bufB[CAPG];

__device__ __forceinline__ float2 cmul(float2 a, float2 b) {
    return make_float2(a.x*b.x - a.y*b.y, a.x*b.y + a.y*b.x);
}
__device__ __forceinline__ int clampi(int i, int cap) { return i < cap ? i : cap - 1; }

// ---------------------------------------------------------------------------
// Kernel 1: coil-modulate + centered zero-pad + forward row FFT (512-pt).
// Strided complex loads: component at p[stride*idx] (stride=1 separate
// arrays; stride=2 interleaved complex with xi = xr+1).
// ---------------------------------------------------------------------------
__global__ void __launch_bounds__(256) k_row_fwd(
    const float* __restrict__ xr, const float* __restrict__ xi, int sx,
    const float* __restrict__ mr, const float* __restrict__ mi, int sm_)
{
    __shared__ float2 sa[N1], sb[N1];
    __shared__ float2 tw[256];
    const int t   = threadIdx.x;
    const int h   = blockIdx.x & 255;
    const int img = blockIdx.x >> 8;      // c*NA + a
    const int a   = img % NA;
    const int c   = img / NA;

    { float s, co; __sincosf(-PI_F * (float)t * (1.0f/256.0f), &s, &co);
      tw[t] = make_float2(co, s); }

    {
        const int ix = clampi(a*HH*WW + h*WW + t, NX);
        const int im = clampi(c*HH*WW + h*WW + t, NM);
        float xvr = xr[sx*ix],  xvi = xi[sx*ix];
        float mvr = mr[sm_*im], mvi = mi[sm_*im];
        sa[128 + t] = make_float2(mvr*xvr - mvi*xvi, mvr*xvi + mvi*xvr);
        if (t < 128) { sa[t] = make_float2(0.f,0.f); sa[t+384] = make_float2(0.f,0.f); }
    }
    __syncthreads();

    float2 *cur = sa, *nxt = sb;
    #pragma unroll
    for (int st = 0; st < 9; st++) {
        const int m  = 1 << st;
        const int k  = t & (m - 1);
        const int jm = t - k;
        float2 c0 = cur[jm + k];
        float2 c1 = cur[jm + k + 256];
        float2 w  = tw[jm];
        nxt[2*jm + k]     = make_float2(c0.x + c1.x, c0.y + c1.y);
        float2 df = make_float2(c0.x - c1.x, c0.y - c1.y);
        nxt[2*jm + k + m] = cmul(w, df);
        float2* tmp = cur; cur = nxt; nxt = tmp;
        __syncthreads();
    }
    const int base = img * N2 + (128 + h) * N1;
    g_bufA[clampi(base + t,       CAPG)] = cur[t];
    g_bufA[clampi(base + t + 256, CAPG)] = cur[t + 256];
}

// ---------------------------------------------------------------------------
// Column FFT / IFFT, 4-column tiles, static-smem ping-pong Stockham.
// SRC_A=true : A -> B (forward; input nonzero only rows [128,384))
// SRC_A=false: B -> A (inverse; only rows [128,384) of output written)
// ---------------------------------------------------------------------------
template<bool INV, bool HALF_IN, bool HALF_OUT, bool SRC_A>
__global__ void __launch_bounds__(256) k_col()
{
    __shared__ float2 s0[N1 * 5];
    __shared__ float2 s1[N1 * 5];
    __shared__ float2 tw[256];

    const int t    = threadIdx.x;
    const int col  = t & 3;
    const int r    = t >> 2;                 // 0..63
    const int img  = blockIdx.x >> 7;
    const int col0 = (blockIdx.x & 127) * 4;

    { float s, co;
      __sincosf((INV ? PI_F : -PI_F) * (float)t * (1.0f/256.0f), &s, &co);
      tw[t] = make_float2(co, s); }

    const float2* __restrict__ gin = (SRC_A ? g_bufA : g_bufB) + img * N2;
    if (HALF_IN) {
        #pragma unroll
        for (int q = 0; q < 4; q++) {
            int row = 128 + q*64 + r;
            s0[row*5 + col] = gin[clampi(row*N1 + col0 + col, N2)];
        }
        #pragma unroll
        for (int q = 0; q < 2; q++) {
            int row = q*64 + r;
            s0[row*5 + col]       = make_float2(0.f,0.f);
            s0[(row+384)*5 + col] = make_float2(0.f,0.f);
        }
    } else {
        #pragma unroll
        for (int q = 0; q < 8; q++) {
            int row = q*64 + r;
            s0[row*5 + col] = gin[clampi(row*N1 + col0 + col, N2)];
        }
    }
    __syncthreads();

    float2 *cur = s0, *nxt = s1;
    #pragma unroll
    for (int st = 0; st < 9; st++) {
        const int m = 1 << st;
        #pragma unroll
        for (int q = 0; q < 4; q++) {
            const int bf = q*64 + r;
            const int k  = bf & (m - 1);
            const int jm = bf - k;
            float2 c0 = cur[(jm + k)*5 + col];
            float2 c1 = cur[(jm + k + 256)*5 + col];
            float2 w  = tw[jm];
            nxt[(2*jm + k)*5 + col]     = make_float2(c0.x + c1.x, c0.y + c1.y);
            float2 df = make_float2(c0.x - c1.x, c0.y - c1.y);
            nxt[(2*jm + k + m)*5 + col] = cmul(w, df);
        }
        float2* tmp = cur; cur = nxt; nxt = tmp;
        __syncthreads();
    }

    float2* __restrict__ gout = (SRC_A ? g_bufB : g_bufA) + img * N2;
    if (HALF_OUT) {
        #pragma unroll
        for (int q = 0; q < 4; q++) {
            int row = 128 + q*64 + r;
            gout[clampi(row*N1 + col0 + col, N2)] = cur[row*5 + col];
        }
    } else {
        #pragma unroll
        for (int q = 0; q < 8; q++) {
            int row = q*64 + r;
            gout[clampi(row*N1 + col0 + col, N2)] = cur[row*5 + col];
        }
    }
}

// ---------------------------------------------------------------------------
// Kernel 3: frequency mixing Y[c,ao] = sum_ai Fx[c,ai]*K[ao,ai], IN PLACE on
// g_bufB (per-thread: all ai read to registers before any ao write).
// ---------------------------------------------------------------------------
__global__ void __launch_bounds__(256) k_combine(
    const float* __restrict__ kr, const float* __restrict__ ki, int sk)
{
    const int hw = blockIdx.x * 256 + threadIdx.x;
    float2 K[NA*NA];
    #pragma unroll
    for (int i = 0; i < NA*NA; i++) {
        int idx = clampi(i*N2 + hw, NK);
        K[i] = make_float2(kr[sk*idx], ki[sk*idx]);
    }

    for (int c = 0; c < NC; c++) {
        float2 fx[NA];
        #pragma unroll
        for (int ai = 0; ai < NA; ai++)
            fx[ai] = g_bufB[clampi((c*NA + ai)*N2 + hw, CAPG)];
        #pragma unroll
        for (int ao = 0; ao < NA; ao++) {
            float2 y = make_float2(0.f, 0.f);
            #pragma unroll
            for (int ai = 0; ai < NA; ai++) {
                float2 kk = K[ao*NA + ai];
                float2 f  = fx[ai];
                y.x += f.x*kk.x - f.y*kk.y;
                y.y += f.x*kk.y + f.y*kk.x;
            }
            g_bufB[clampi((c*NA + ao)*N2 + hw, CAPG)] = y;
        }
    }
}

// ---------------------------------------------------------------------------
// Kernel 5: inverse row FFT + centered crop + scale (A rows [128,384) ->
// cropped images in dead g_bufB front region). scale = 4/512^2.
// ---------------------------------------------------------------------------
__global__ void __launch_bounds__(256) k_row_inv()
{
    __shared__ float2 sa[N1], sb[N1];
    __shared__ float2 tw[256];
    const int t   = threadIdx.x;
    const int h   = blockIdx.x & 255;
    const int img = blockIdx.x >> 8;

    { float s, co; __sincosf(PI_F * (float)t * (1.0f/256.0f), &s, &co);
      tw[t] = make_float2(co, s); }

    const int base = img * N2 + (128 + h) * N1;
    sa[t]       = g_bufA[clampi(base + t,       CAPG)];
    sa[t + 256] = g_bufA[clampi(base + t + 256, CAPG)];
    __syncthreads();

    float2 *cur = sa, *nxt = sb;
    #pragma unroll
    for (int st = 0; st < 9; st++) {
        const int m  = 1 << st;
        const int k  = t & (m - 1);
        const int jm = t - k;
        float2 c0 = cur[jm + k];
        float2 c1 = cur[jm + k + 256];
        float2 w  = tw[jm];
        nxt[2*jm + k]     = make_float2(c0.x + c1.x, c0.y + c1.y);
        float2 df = make_float2(c0.x - c1.x, c0.y - c1.y);
        nxt[2*jm + k + m] = cmul(w, df);
        float2* tmp = cur; cur = nxt; nxt = tmp;
        __syncthreads();
    }
    const float scale = 4.0f / (512.0f * 512.0f);
    float2 v = cur[128 + t];
    g_bufB[clampi(img * HH*WW + h * WW + t, CAPG)] =
        make_float2(v.x * scale, v.y * scale);
}

// ---------------------------------------------------------------------------
// Kernel 6: coil combine out[a] = sum_c conj(mps[c]) * Y[c,a].
// PLANAR float32 output: out[0:NX] = real parts, out[NX:2NX] = imag parts
// (harness-side stack([y.real, y.imag]) layout). Guarded by float cap capf.
// ---------------------------------------------------------------------------
__global__ void __launch_bounds__(256) k_final(
    const float* __restrict__ mr, const float* __restrict__ mi, int sm_,
    float* __restrict__ out, int capf)
{
    const int hw = blockIdx.x * 256 + threadIdx.x;
    float2 acc[NA];
    #pragma unroll
    for (int a = 0; a < NA; a++) acc[a] = make_float2(0.f, 0.f);

    for (int c = 0; c < NC; c++) {
        int im = clampi(c*HH*WW + hw, NM);
        float2 m = make_float2(mr[sm_*im], mi[sm_*im]);
        #pragma unroll
        for (int a = 0; a < NA; a++) {
            float2 y = g_bufB[clampi((c*NA + a)*HH*WW + hw, CAPG)];
            acc[a].x += m.x*y.x + m.y*y.y;   // conj(m) * y
            acc[a].y += m.x*y.y - m.y*y.x;
        }
    }
    #pragma unroll
    for (int a = 0; a < NA; a++) {
        int idx = a*HH*WW + hw;
        if (idx < capf)      out[idx]      = acc[a].x;
        if (NX + idx < capf) out[NX + idx] = acc[a].y;
    }
}

// ---------------------------------------------------------------------------
extern "C" void kernel_launch(void* const* d_in, const int* in_sizes, int n_in,
                              void* d_out, int out_size)
{
    // Model (rebuilt after crash evidence was shown to be flaky):
    //  - inputs in dict/metadata order (x_r, x_i, mps_r, mps_i, kern_r,
    //    kern_i); within each size family the REAL array occurs first;
    //  - in_sizes are element counts per the stub docs (4E also accepted);
    //  - OUTPUT IS PLANAR [2, A, H, W]: R6 executed with this exact binding
    //    and produced rel_err = sqrt(2) (norm kept, correlation 0) — the
    //    interleaved-vs-planar scramble signature. Only k_final changed.
    const float *xr = 0, *xi = 0, *mr = 0, *mi = 0, *kr = 0, *ki = 0;
    int sx = 1, sm_ = 1, sk = 1;

    if (n_in >= 6) {
        for (int i = 0; i < n_in; i++) {
            const float* p = (const float*)d_in[i];
            const long long sz = in_sizes[i];
            if (sz == NX || sz == 4LL*NX)      { if (!xr) xr = p; else if (!xi) xi = p; }
            else if (sz == NM || sz == 4LL*NM) { if (!mr) mr = p; else if (!mi) mi = p; }
            else if (sz == NK || sz == 4LL*NK) { if (!kr) kr = p; else if (!ki) ki = p; }
        }
        if (!xr || !xi || !mr || !mi || !kr || !ki) {
            // Positional fallback in dict order.
            xr = (const float*)d_in[0]; xi = (const float*)d_in[1];
            mr = (const float*)d_in[2]; mi = (const float*)d_in[3];
            kr = (const float*)d_in[4]; ki = (const float*)d_in[5];
        }
    } else if (n_in >= 3) {
        // Three packed complex arrays: interleaved (re,im) float pairs.
        for (int i = 0; i < 3; i++) {
            const float* p = (const float*)d_in[i];
            const long long sz = in_sizes[i];
            if (sz == NX || sz == 2LL*NX || sz == 8LL*NX)      { xr = p; xi = p + 1; sx = 2; }
            else if (sz == NM || sz == 2LL*NM || sz == 8LL*NM) { mr = p; mi = p + 1; sm_ = 2; }
            else if (sz == NK || sz == 2LL*NK || sz == 8LL*NK) { kr = p; ki = p + 1; sk = 2; }
        }
        if (!xr || !mr || !kr) { return; }  // unknown packing: no crash, poisoned out
    } else {
        return;  // unknown packing: leave d_out poisoned (diagnostic, no crash)
    }

    // Output float capacity: expected out_size = 2*NX float32 elements.
    int capf = (out_size >= 2*NX) ? 2*NX : out_size;

    // 1. modulate + pad + forward row FFT        (-> A rows 128..383)
    k_row_fwd<<<NIMG * HH, 256>>>(xr, xi, sx, mr, mi, sm_);
    // 2. forward column FFT                      (A -> B, full)
    k_col<false, true, false, true><<<NIMG * 128, 256>>>();
    // 3. frequency-domain kernel mixing          (B in place)
    k_combine<<<N2 / 256, 256>>>(kr, ki, sk);
    // 4. inverse column FFT                      (B -> A rows 128..383)
    k_col<true, false, true, false><<<NIMG * 128, 256>>>();
    // 5. inverse row FFT + crop + scale          (A -> B front region)
    k_row_inv<<<NIMG * HH, 256>>>();
    // 6. coil combine (PLANAR output)            (B front + mps -> out)
    k_final<<<HH * WW / 256, 256>>>(mr, mi, sm_, (float*)d_out, capf);
}

// round 14
// speedup vs baseline: 1.8881x; 1.8881x over previous
#include <cuda_runtime.h>

#define PI_F 3.14159265358979f
#define N1   512
#define N2   (512*512)
#define HH   256
#define WW   256
#define NA   5
#define NC   12
#define NIMG 60            // NC*NA

#define NX   (NA*HH*WW)    // 327680
#define NM   (NC*HH*WW)    // 786432
#define NK   (NA*NA*N2)    // 6553600
#define CAPG (NIMG*N2)     // scratch capacity in float2

// Scratch (static device globals: allocation-free, graph-safe). 2 x 126 MB.
__device__ float2 g_bufA[CAPG];
__device__ float2 g_bufB[CAPG];

__device__ __forceinline__ float2 cmul(float2 a, float2 b) {
    return make_float2(a.x*b.x - a.y*b.y, a.x*b.y + a.y*b.x);
}
__device__ __forceinline__ float2 cadd(float2 a, float2 b) {
    return make_float2(a.x + b.x, a.y + b.y);
}
__device__ __forceinline__ float2 csub(float2 a, float2 b) {
    return make_float2(a.x - b.x, a.y - b.y);
}
// -i*z (forward) / +i*z (inverse)
template<bool INV>
__device__ __forceinline__ float2 rot90(float2 z) {
    return INV ? make_float2(-z.y, z.x) : make_float2(z.y, -z.x);
}
__device__ __forceinline__ int clampi(int i, int cap) { return i < cap ? i : cap - 1; }

// ---------------------------------------------------------------------------
// Kernel 1: modulate + centered pad + forward row FFT. Radix-4 Stockham,
// 2 rows per block (rp = t&1 interleave -> conflict-optimal smem).
// Stage 0 (m=1) fused with the gmem load: padded positions [0,128) and
// [384,512) are zero => a0 = a3 = 0. Writes g_bufA rows [128,384).
// ---------------------------------------------------------------------------
__global__ void __launch_bounds__(256) k_row_fwd4(
    const float* __restrict__ xr, const float* __restrict__ xi, int sx,
    const float* __restrict__ mr, const float* __restrict__ mi, int sm_)
{
    __shared__ float2 s0[1024], s1[1024];   // [pos*2 + rp]
    __shared__ float2 tw[256];
    const int t   = threadIdx.x;
    const int rp  = t & 1;
    const int tr  = t >> 1;                 // 0..127 (butterfly index)
    const int img = blockIdx.x >> 7;        // c*NA + a
    const int hb  = blockIdx.x & 127;
    const int a   = img % NA;
    const int c   = img / NA;
    const int h   = hb * 2 + rp;

    { float s, co; __sincosf(-PI_F * (float)t * (1.0f/256.0f), &s, &co);
      tw[t] = make_float2(co, s); }
    __syncthreads();

    // stage 0 (m=1): a1 = padded[tr+128] = xm[tr], a2 = padded[tr+256] = xm[tr+128]
    {
        const int bx = a*HH*WW + h*WW;
        const int bm = c*HH*WW + h*WW;
        int i1x = clampi(bx + tr, NX),       i1m = clampi(bm + tr, NM);
        int i2x = clampi(bx + tr + 128, NX), i2m = clampi(bm + tr + 128, NM);
        float x1r = xr[sx*i1x], x1i = xi[sx*i1x];
        float m1r = mr[sm_*i1m], m1i = mi[sm_*i1m];
        float x2r = xr[sx*i2x], x2i = xi[sx*i2x];
        float m2r = mr[sm_*i2m], m2i = mi[sm_*i2m];
        float2 a1 = make_float2(m1r*x1r - m1i*x1i, m1r*x1i + m1i*x1r);
        float2 a2 = make_float2(m2r*x2r - m2i*x2i, m2r*x2i + m2i*x2r);
        float2 w1 = tw[tr], w2 = tw[2*tr];
        float2 w3 = cmul(w1, w2);
        float2 t0 = a2, t1 = a1;
        float2 u0 = make_float2(-a2.x, -a2.y);
        float2 u1 = rot90<false>(a1);
        int o = 4*tr;
        s0[(o    )*2 + rp] = cadd(t0, t1);
        s0[(o + 1)*2 + rp] = cmul(w1, cadd(u0, u1));
        s0[(o + 2)*2 + rp] = cmul(w2, csub(t0, t1));
        s0[(o + 3)*2 + rp] = cmul(w3, csub(u0, u1));
    }
    __syncthreads();

    float2 *cur = s0, *nxt = s1;
    #pragma unroll
    for (int st = 1; st < 4; st++) {
        const int m  = 1 << (2*st);         // 4, 16, 64
        const int k  = tr & (m - 1);
        const int jm = tr - k;
        float2 a0 = cur[(tr      )*2 + rp];
        float2 a1 = cur[(tr + 128)*2 + rp];
        float2 a2 = cur[(tr + 256)*2 + rp];
        float2 a3 = cur[(tr + 384)*2 + rp];
        float2 w1 = tw[jm], w2 = tw[2*jm];
        float2 w3 = cmul(w1, w2);
        float2 t0 = cadd(a0, a2), t1 = cadd(a1, a3);
        float2 u0 = csub(a0, a2), u1 = rot90<false>(csub(a1, a3));
        int o = 4*jm + k;
        nxt[(o      )*2 + rp] = cadd(t0, t1);
        nxt[(o +   m)*2 + rp] = cmul(w1, cadd(u0, u1));
        nxt[(o + 2*m)*2 + rp] = cmul(w2, csub(t0, t1));
        nxt[(o + 3*m)*2 + rp] = cmul(w3, csub(u0, u1));
        float2* tmp = cur; cur = nxt; nxt = tmp;
        __syncthreads();
    }

    // final radix-2 (m=256, tw[0]=1) fused with gmem store
    {
        const int gbase = img * N2 + (128 + h) * N1;
        #pragma unroll
        for (int q = 0; q < 2; q++) {
            int bf = tr + 128*q;
            float2 A = cur[(bf      )*2 + rp];
            float2 B = cur[(bf + 256)*2 + rp];
            g_bufA[clampi(gbase + bf,       CAPG)] = cadd(A, B);
            g_bufA[clampi(gbase + bf + 256, CAPG)] = csub(A, B);
        }
    }
}

// ---------------------------------------------------------------------------
// Kernel 2: forward column FFT (A -> B). Radix-4, 4 columns per block,
// stride-4 smem layout (conflict-optimal). Stage 0 fused with gmem load
// (rows [0,128) and [384,512) are zero). Full output.
// ---------------------------------------------------------------------------
__global__ void __launch_bounds__(256) k_col4_fwd()
{
    __shared__ float2 s0[2048], s1[2048];   // [row*4 + col]
    __shared__ float2 tw[256];
    const int t    = threadIdx.x;
    const int col  = t & 3;
    const int r    = t >> 2;                // 0..63
    const int img  = blockIdx.x >> 7;
    const int col0 = (blockIdx.x & 127) * 4;

    { float s, co; __sincosf(-PI_F * (float)t * (1.0f/256.0f), &s, &co);
      tw[t] = make_float2(co, s); }
    __syncthreads();

    const float2* __restrict__ gin = g_bufA + img * N2 + col0 + col;

    // stage 0 (m=1) fused with load: a0 = a3 = 0
    #pragma unroll
    for (int q = 0; q < 2; q++) {
        int bf = q*64 + r;                  // 0..127
        float2 a1 = gin[clampi((bf + 128)*N1, N2 - 1) /*row idx*/];
        float2 a2 = gin[(bf + 256)*N1];
        float2 w1 = tw[bf], w2 = tw[2*bf];
        float2 w3 = cmul(w1, w2);
        float2 t0 = a2, t1 = a1;
        float2 u0 = make_float2(-a2.x, -a2.y);
        float2 u1 = rot90<false>(a1);
        int o = 4*bf;
        s0[(o    )*4 + col] = cadd(t0, t1);
        s0[(o + 1)*4 + col] = cmul(w1, cadd(u0, u1));
        s0[(o + 2)*4 + col] = cmul(w2, csub(t0, t1));
        s0[(o + 3)*4 + col] = cmul(w3, csub(u0, u1));
    }
    __syncthreads();

    float2 *cur = s0, *nxt = s1;
    #pragma unroll
    for (int st = 1; st < 4; st++) {
        const int m = 1 << (2*st);          // 4, 16, 64
        #pragma unroll
        for (int q = 0; q < 2; q++) {
            int bf = q*64 + r;
            int k  = bf & (m - 1);
            int jm = bf - k;
            float2 a0 = cur[(bf      )*4 + col];
            float2 a1 = cur[(bf + 128)*4 + col];
            float2 a2 = cur[(bf + 256)*4 + col];
            float2 a3 = cur[(bf + 384)*4 + col];
            float2 w1 = tw[jm], w2 = tw[2*jm];
            float2 w3 = cmul(w1, w2);
            float2 t0 = cadd(a0, a2), t1 = cadd(a1, a3);
            float2 u0 = csub(a0, a2), u1 = rot90<false>(csub(a1, a3));
            int o = 4*jm + k;
            nxt[(o      )*4 + col] = cadd(t0, t1);
            nxt[(o +   m)*4 + col] = cmul(w1, cadd(u0, u1));
            nxt[(o + 2*m)*4 + col] = cmul(w2, csub(t0, t1));
            nxt[(o + 3*m)*4 + col] = cmul(w3, csub(u0, u1));
        }
        float2* tmp = cur; cur = nxt; nxt = tmp;
        __syncthreads();
    }

    // final radix-2 fused with store (full output)
    float2* __restrict__ gout = g_bufB + img * N2 + col0 + col;
    #pragma unroll
    for (int q = 0; q < 4; q++) {
        int bf = q*64 + r;                  // 0..255
        float2 A = cur[(bf      )*4 + col];
        float2 B = cur[(bf + 256)*4 + col];
        gout[(bf      )*N1] = cadd(A, B);
        gout[(bf + 256)*N1] = csub(A, B);
    }
}

// ---------------------------------------------------------------------------
// Kernel 4: inverse column FFT (B -> A). Full input; only output rows
// [128,384) needed -> final radix-2 computes exactly that half.
// ---------------------------------------------------------------------------
__global__ void __launch_bounds__(256) k_col4_inv()
{
    __shared__ float2 s0[2048], s1[2048];
    __shared__ float2 tw[256];
    const int t    = threadIdx.x;
    const int col  = t & 3;
    const int r    = t >> 2;
    const int img  = blockIdx.x >> 7;
    const int col0 = (blockIdx.x & 127) * 4;

    { float s, co; __sincosf(PI_F * (float)t * (1.0f/256.0f), &s, &co);
      tw[t] = make_float2(co, s); }
    __syncthreads();

    const float2* __restrict__ gin = g_bufB + img * N2 + col0 + col;

    // stage 0 (m=1) fused with full load
    #pragma unroll
    for (int q = 0; q < 2; q++) {
        int bf = q*64 + r;
        float2 a0 = gin[(bf      )*N1];
        float2 a1 = gin[(bf + 128)*N1];
        float2 a2 = gin[(bf + 256)*N1];
        float2 a3 = gin[(bf + 384)*N1];
        float2 w1 = tw[bf], w2 = tw[2*bf];
        float2 w3 = cmul(w1, w2);
        float2 t0 = cadd(a0, a2), t1 = cadd(a1, a3);
        float2 u0 = csub(a0, a2), u1 = rot90<true>(csub(a1, a3));
        int o = 4*bf;
        s0[(o    )*4 + col] = cadd(t0, t1);
        s0[(o + 1)*4 + col] = cmul(w1, cadd(u0, u1));
        s0[(o + 2)*4 + col] = cmul(w2, csub(t0, t1));
        s0[(o + 3)*4 + col] = cmul(w3, csub(u0, u1));
    }
    __syncthreads();

    float2 *cur = s0, *nxt = s1;
    #pragma unroll
    for (int st = 1; st < 4; st++) {
        const int m = 1 << (2*st);
        #pragma unroll
        for (int q = 0; q < 2; q++) {
            int bf = q*64 + r;
            int k  = bf & (m - 1);
            int jm = bf - k;
            float2 a0 = cur[(bf      )*4 + col];
            float2 a1 = cur[(bf + 128)*4 + col];
            float2 a2 = cur[(bf + 256)*4 + col];
            float2 a3 = cur[(bf + 384)*4 + col];
            float2 w1 = tw[jm], w2 = tw[2*jm];
            float2 w3 = cmul(w1, w2);
            float2 t0 = cadd(a0, a2), t1 = cadd(a1, a3);
            float2 u0 = csub(a0, a2), u1 = rot90<true>(csub(a1, a3));
            int o = 4*jm + k;
            nxt[(o      )*4 + col] = cadd(t0, t1);
            nxt[(o +   m)*4 + col] = cmul(w1, cadd(u0, u1));
            nxt[(o + 2*m)*4 + col] = cmul(w2, csub(t0, t1));
            nxt[(o + 3*m)*4 + col] = cmul(w3, csub(u0, u1));
        }
        float2* tmp = cur; cur = nxt; nxt = tmp;
        __syncthreads();
    }

    // final radix-2: only rows [128,384).
    // bf in [0,128)  -> row bf+256 = A - B ; bf in [128,256) -> row bf = A + B
    float2* __restrict__ gout = g_bufA + img * N2 + col0 + col;
    #pragma unroll
    for (int q = 0; q < 4; q++) {
        int bf = q*64 + r;
        float2 A = cur[(bf      )*4 + col];
        float2 B = cur[(bf + 256)*4 + col];
        if (bf < 128) gout[(bf + 256)*N1] = csub(A, B);
        else          gout[(bf      )*N1] = cadd(A, B);
    }
}

// ---------------------------------------------------------------------------
// Kernel 3: frequency mixing, IN PLACE on g_bufB (unchanged from R13).
// ---------------------------------------------------------------------------
__global__ void __launch_bounds__(256) k_combine(
    const float* __restrict__ kr, const float* __restrict__ ki, int sk)
{
    const int hw = blockIdx.x * 256 + threadIdx.x;
    float2 K[NA*NA];
    #pragma unroll
    for (int i = 0; i < NA*NA; i++) {
        int idx = clampi(i*N2 + hw, NK);
        K[i] = make_float2(kr[sk*idx], ki[sk*idx]);
    }

    for (int c = 0; c < NC; c++) {
        float2 fx[NA];
        #pragma unroll
        for (int ai = 0; ai < NA; ai++)
            fx[ai] = g_bufB[clampi((c*NA + ai)*N2 + hw, CAPG)];
        #pragma unroll
        for (int ao = 0; ao < NA; ao++) {
            float2 y = make_float2(0.f, 0.f);
            #pragma unroll
            for (int ai = 0; ai < NA; ai++) {
                float2 kk = K[ao*NA + ai];
                float2 f  = fx[ai];
                y.x += f.x*kk.x - f.y*kk.y;
                y.y += f.x*kk.y + f.y*kk.x;
            }
            g_bufB[clampi((c*NA + ao)*N2 + hw, CAPG)] = y;
        }
    }
}

// ---------------------------------------------------------------------------
// Kernel 5: inverse row FFT + crop + scale (A rows [128,384) -> B front).
// Radix-4, 2 rows per block. Final stage computes only cols [128,384).
// ---------------------------------------------------------------------------
__global__ void __launch_bounds__(256) k_row_inv4()
{
    __shared__ float2 s0[1024], s1[1024];
    __shared__ float2 tw[256];
    const int t   = threadIdx.x;
    const int rp  = t & 1;
    const int tr  = t >> 1;                 // 0..127
    const int img = blockIdx.x >> 7;
    const int hb  = blockIdx.x & 127;
    const int h   = hb * 2 + rp;

    { float s, co; __sincosf(PI_F * (float)t * (1.0f/256.0f), &s, &co);
      tw[t] = make_float2(co, s); }
    __syncthreads();

    const float2* __restrict__ gin = g_bufA + img * N2 + (128 + h) * N1;

    // stage 0 (m=1) fused with full load
    {
        float2 a0 = gin[tr      ];
        float2 a1 = gin[tr + 128];
        float2 a2 = gin[tr + 256];
        float2 a3 = gin[tr + 384];
        float2 w1 = tw[tr], w2 = tw[2*tr];
        float2 w3 = cmul(w1, w2);
        float2 t0 = cadd(a0, a2), t1 = cadd(a1, a3);
        float2 u0 = csub(a0, a2), u1 = rot90<true>(csub(a1, a3));
        int o = 4*tr;
        s0[(o    )*2 + rp] = cadd(t0, t1);
        s0[(o + 1)*2 + rp] = cmul(w1, cadd(u0, u1));
        s0[(o + 2)*2 + rp] = cmul(w2, csub(t0, t1));
        s0[(o + 3)*2 + rp] = cmul(w3, csub(u0, u1));
    }
    __syncthreads();

    float2 *cur = s0, *nxt = s1;
    #pragma unroll
    for (int st = 1; st < 4; st++) {
        const int m  = 1 << (2*st);
        const int k  = tr & (m - 1);
        const int jm = tr - k;
        float2 a0 = cur[(tr      )*2 + rp];
        float2 a1 = cur[(tr + 128)*2 + rp];
        float2 a2 = cur[(tr + 256)*2 + rp];
        float2 a3 = cur[(tr + 384)*2 + rp];
        float2 w1 = tw[jm], w2 = tw[2*jm];
        float2 w3 = cmul(w1, w2);
        float2 t0 = cadd(a0, a2), t1 = cadd(a1, a3);
        float2 u0 = csub(a0, a2), u1 = rot90<true>(csub(a1, a3));
        int o = 4*jm + k;
        nxt[(o      )*2 + rp] = cadd(t0, t1);
        nxt[(o +   m)*2 + rp] = cmul(w1, cadd(u0, u1));
        nxt[(o + 2*m)*2 + rp] = cmul(w2, csub(t0, t1));
        nxt[(o + 3*m)*2 + rp] = cmul(w3, csub(u0, u1));
        float2* tmp = cur; cur = nxt; nxt = tmp;
        __syncthreads();
    }

    // final radix-2: only padded cols [128,384), crop to [0,256), scale.
    const float scale = 4.0f / (512.0f * 512.0f);
    float2* __restrict__ gout = g_bufB + img * HH*WW + h * WW;
    {
        // q=0: bf = tr in [0,128)  -> padded col bf+256 -> crop idx tr+128 (A-B)
        float2 A = cur[(tr      )*2 + rp];
        float2 B = cur[(tr + 256)*2 + rp];
        float2 v = csub(A, B);
        gout[tr + 128] = make_float2(v.x * scale, v.y * scale);
        // q=1: bf = tr+128 in [128,256) -> padded col bf -> crop idx tr (A+B)
        float2 A2 = cur[(tr + 128)*2 + rp];
        float2 B2 = cur[(tr + 384)*2 + rp];
        float2 w = cadd(A2, B2);
        gout[tr] = make_float2(w.x * scale, w.y * scale);
    }
}

// ---------------------------------------------------------------------------
// Kernel 6: coil combine, PLANAR float32 output (unchanged from R13).
// ---------------------------------------------------------------------------
__global__ void __launch_bounds__(256) k_final(
    const float* __restrict__ mr, const float* __restrict__ mi, int sm_,
    float* __restrict__ out, int capf)
{
    const int hw = blockIdx.x * 256 + threadIdx.x;
    float2 acc[NA];
    #pragma unroll
    for (int a = 0; a < NA; a++) acc[a] = make_float2(0.f, 0.f);

    for (int c = 0; c < NC; c++) {
        int im = clampi(c*HH*WW + hw, NM);
        float2 m = make_float2(mr[sm_*im], mi[sm_*im]);
        #pragma unroll
        for (int a = 0; a < NA; a++) {
            float2 y = g_bufB[clampi((c*NA + a)*HH*WW + hw, CAPG)];
            acc[a].x += m.x*y.x + m.y*y.y;   // conj(m) * y
            acc[a].y += m.x*y.y - m.y*y.x;
        }
    }
    #pragma unroll
    for (int a = 0; a < NA; a++) {
        int idx = a*HH*WW + hw;
        if (idx < capf)      out[idx]      = acc[a].x;
        if (NX + idx < capf) out[NX + idx] = acc[a].y;
    }
}

// ---------------------------------------------------------------------------
extern "C" void kernel_launch(void* const* d_in, const int* in_sizes, int n_in,
                              void* d_out, int out_size)
{
    // Confirmed model (R13 PASSED, rel_err 7.5e-7): dict-order inputs
    // (x_r, x_i, mps_r, mps_i, kern_r, kern_i), real first within each size
    // family; sizes as elements (E) or bytes (4E); PLANAR [2,A,H,W] output.
    const float *xr = 0, *xi = 0, *mr = 0, *mi = 0, *kr = 0, *ki = 0;
    int sx = 1, sm_ = 1, sk = 1;

    if (n_in >= 6) {
        for (int i = 0; i < n_in; i++) {
            const float* p = (const float*)d_in[i];
            const long long sz = in_sizes[i];
            if (sz == NX || sz == 4LL*NX)      { if (!xr) xr = p; else if (!xi) xi = p; }
            else if (sz == NM || sz == 4LL*NM) { if (!mr) mr = p; else if (!mi) mi = p; }
            else if (sz == NK || sz == 4LL*NK) { if (!kr) kr = p; else if (!ki) ki = p; }
        }
        if (!xr || !xi || !mr || !mi || !kr || !ki) {
            xr = (const float*)d_in[0]; xi = (const float*)d_in[1];
            mr = (const float*)d_in[2]; mi = (const float*)d_in[3];
            kr = (const float*)d_in[4]; ki = (const float*)d_in[5];
        }
    } else if (n_in >= 3) {
        for (int i = 0; i < 3; i++) {
            const float* p = (const float*)d_in[i];
            const long long sz = in_sizes[i];
            if (sz == NX || sz == 2LL*NX || sz == 8LL*NX)      { xr = p; xi = p + 1; sx = 2; }
            else if (sz == NM || sz == 2LL*NM || sz == 8LL*NM) { mr = p; mi = p + 1; sm_ = 2; }
            else if (sz == NK || sz == 2LL*NK || sz == 8LL*NK) { kr = p; ki = p + 1; sk = 2; }
        }
        if (!xr || !mr || !kr) { return; }
    } else {
        return;
    }

    int capf = (out_size >= 2*NX) ? 2*NX : out_size;

    // 1. modulate + pad + forward row FFT        (-> A rows 128..383)
    k_row_fwd4<<<NIMG * 128, 256>>>(xr, xi, sx, mr, mi, sm_);
    // 2. forward column FFT                      (A -> B, full)
    k_col4_fwd<<<NIMG * 128, 256>>>();
    // 3. frequency-domain kernel mixing          (B in place)
    k_combine<<<N2 / 256, 256>>>(kr, ki, sk);
    // 4. inverse column FFT                      (B -> A rows 128..383)
    k_col4_inv<<<NIMG * 128, 256>>>();
    // 5. inverse row FFT + crop + scale          (A -> B front region)
    k_row_inv4<<<NIMG * 128, 256>>>();
    // 6. coil combine (PLANAR output)            (B front + mps -> out)
    k_final<<<HH * WW / 256, 256>>>(mr, mi, sm_, (float*)d_out, capf);
}

// round 16
// speedup vs baseline: 2.9758x; 1.5761x over previous
#include <cuda_runtime.h>

#define PI_F   3.14159265358979f
#define RSQ2_F 0.70710678118654752f
#define N1   512
#define N2   (512*512)
#define HH   256
#define WW   256
#define NA   5
#define NC   12
#define NIMG 60            // NC*NA

#define NX   (NA*HH*WW)    // 327680
#define NM   (NC*HH*WW)    // 786432
#define NK   (NA*NA*N2)    // 6553600
#define CAPG (NIMG*N2)     // scratch capacity in float2

// Scratch (static device globals: allocation-free, graph-safe). 2 x 126 MB.
__device__ float2 g_bufA[CAPG];
__device__ float2 g_bufB[CAPG];

__device__ __forceinline__ float2 cmul(float2 a, float2 b) {
    return make_float2(a.x*b.x - a.y*b.y, a.x*b.y + a.y*b.x);
}
__device__ __forceinline__ float2 cadd(float2 a, float2 b) {
    return make_float2(a.x + b.x, a.y + b.y);
}
__device__ __forceinline__ float2 csub(float2 a, float2 b) {
    return make_float2(a.x - b.x, a.y - b.y);
}
// forward: -i*z ; inverse: +i*z
template<bool INV>
__device__ __forceinline__ float2 rot90(float2 z) {
    return INV ? make_float2(-z.y, z.x) : make_float2(z.y, -z.x);
}
// forward: (1-i)/sqrt2 * z ; inverse: (1+i)/sqrt2 * z
template<bool INV>
__device__ __forceinline__ float2 mul_w1(float2 z) {
    return INV ? make_float2((z.x - z.y)*RSQ2_F, (z.x + z.y)*RSQ2_F)
               : make_float2((z.x + z.y)*RSQ2_F, (z.y - z.x)*RSQ2_F);
}
// forward: -(1+i)/sqrt2 * z ; inverse: (-1+i)/sqrt2 * z
template<bool INV>
__device__ __forceinline__ float2 mul_w3(float2 z) {
    return INV ? make_float2(-(z.x + z.y)*RSQ2_F, (z.x - z.y)*RSQ2_F)
               : make_float2((z.y - z.x)*RSQ2_F, -(z.x + z.y)*RSQ2_F);
}
__device__ __forceinline__ int clampi(int i, int cap) { return i < cap ? i : cap - 1; }

// XOR swizzle on smem float2 index (4-lane interleave): keeps stride-64
// reads conflict-free, reduces stage write conflicts 8-way -> 2-way.
__device__ __forceinline__ int swz(int pos, int lane) {
    return ((pos << 2) | lane) ^ (((pos >> 3) & 7) << 2);
}

// 8-point DIF butterfly, natural-order outputs y[e] = sum_f a[f] w8^(e f),
// w8 = exp(-+ 2 pi i/8). Verified against closed forms of Y1, Y2, Y4.
template<bool INV>
__device__ __forceinline__ void bfly8(const float2* a, float2* y) {
    float2 t0 = cadd(a[0], a[4]);
    float2 t1 = cadd(a[1], a[5]);
    float2 t2 = cadd(a[2], a[6]);
    float2 t3 = cadd(a[3], a[7]);
    float2 t4 = csub(a[0], a[4]);
    float2 t5 = mul_w1<INV>(csub(a[1], a[5]));
    float2 t6 = rot90<INV>(csub(a[2], a[6]));
    float2 t7 = mul_w3<INV>(csub(a[3], a[7]));
    float2 u0 = cadd(t0, t2);
    float2 u1 = cadd(t1, t3);
    float2 u2 = csub(t0, t2);
    float2 u3 = rot90<INV>(csub(t1, t3));
    float2 u4 = cadd(t4, t6);
    float2 u5 = cadd(t5, t7);
    float2 u6 = csub(t4, t6);
    float2 u7 = rot90<INV>(csub(t5, t7));
    y[0] = cadd(u0, u1);  y[4] = csub(u0, u1);
    y[2] = cadd(u2, u3);  y[6] = csub(u2, u3);
    y[1] = cadd(u4, u5);  y[5] = csub(u4, u5);
    y[3] = cadd(u6, u7);  y[7] = csub(u6, u7);
}

// Fill 512-entry twiddle table tw[i] = exp(sgn * 2 pi i * i / 512).
template<bool INV>
__device__ __forceinline__ void fill_tw(float2* tw, int t) {
    #pragma unroll
    for (int i = t; i < 512; i += 256) {
        float s, c;
        __sincosf((INV ? PI_F : -PI_F) * (float)i * (1.0f/256.0f), &s, &c);
        tw[i] = make_float2(c, s);
    }
}

// ---------------------------------------------------------------------------
// Kernel 1: modulate + centered pad + forward row FFT. Radix-8 Stockham,
// 4 rows/block, 64 threads/row. Stage 0 fused with load (pad zeros),
// stage 2 fused with store. Writes g_bufA rows [128,384).
// ---------------------------------------------------------------------------
__global__ void __launch_bounds__(256) k_row_fwd8(
    const float* __restrict__ xr, const float* __restrict__ xi, int sx,
    const float* __restrict__ mr, const float* __restrict__ mi, int sm_)
{
    __shared__ float2 s0[2048], s1[2048];
    __shared__ float2 tw[512];
    const int t    = threadIdx.x;
    const int lane = t & 3;
    const int j    = t >> 2;               // 0..63
    const int img  = blockIdx.x >> 6;      // c*NA + a
    const int a    = img % NA;
    const int c    = img / NA;
    const int h    = (blockIdx.x & 63) * 4 + lane;

    fill_tw<false>(tw, t);
    __syncthreads();

    float2 av[8], y[8];

    // stage m=1 fused with modulated load: padded[p]=xm[p-128] on [128,384)
    {
        const int bx = a*HH*WW + h*WW;
        const int bm = c*HH*WW + h*WW;
        av[0] = av[1] = av[6] = av[7] = make_float2(0.f, 0.f);
        #pragma unroll
        for (int f = 2; f <= 5; f++) {
            int cix = j + 64*(f - 2);      // 0..255
            int ixx = sx  * (bx + cix);
            int ixm = sm_ * (bm + cix);
            float xvr = xr[ixx], xvi = xi[ixx];
            float mvr = mr[ixm], mvi = mi[ixm];
            av[f] = make_float2(mvr*xvr - mvi*xvi, mvr*xvi + mvi*xvr);
        }
        bfly8<false>(av, y);
        #pragma unroll
        for (int e = 0; e < 8; e++)
            s0[swz(8*j + e, lane)] = cmul(tw[e*j], y[e]);
    }
    __syncthreads();

    // stage m=8
    {
        const int k  = j & 7;
        const int jm = j - k;
        #pragma unroll
        for (int f = 0; f < 8; f++) av[f] = s0[swz(j + 64*f, lane)];
        bfly8<false>(av, y);
        #pragma unroll
        for (int e = 0; e < 8; e++)
            s1[swz(8*jm + k + 8*e, lane)] = cmul(tw[e*jm], y[e]);
    }
    __syncthreads();

    // stage m=64 (twiddle-free) fused with store of full row
    {
        #pragma unroll
        for (int f = 0; f < 8; f++) av[f] = s1[swz(j + 64*f, lane)];
        bfly8<false>(av, y);
        float2* __restrict__ gout = g_bufA + img * N2 + (128 + h) * N1;
        #pragma unroll
        for (int e = 0; e < 8; e++) gout[j + 64*e] = y[e];
    }
}

// ---------------------------------------------------------------------------
// Kernel 2: forward column FFT (A -> B). Radix-8, 4 cols/block.
// Stage 0 fused with load (rows outside [128,384) are zero). Full output.
// ---------------------------------------------------------------------------
__global__ void __launch_bounds__(256) k_col8_fwd()
{
    __shared__ float2 s0[2048], s1[2048];
    __shared__ float2 tw[512];
    const int t    = threadIdx.x;
    const int lane = t & 3;
    const int j    = t >> 2;
    const int img  = blockIdx.x >> 7;
    const int col0 = (blockIdx.x & 127) * 4;

    fill_tw<false>(tw, t);
    __syncthreads();

    float2 av[8], y[8];
    const float2* __restrict__ gin = g_bufA + img * N2 + col0 + lane;

    // stage m=1 fused with load: a0=a1=a6=a7 = 0
    {
        av[0] = av[1] = av[6] = av[7] = make_float2(0.f, 0.f);
        av[2] = gin[(j + 128)*N1];
        av[3] = gin[(j + 192)*N1];
        av[4] = gin[(j + 256)*N1];
        av[5] = gin[(j + 320)*N1];
        bfly8<false>(av, y);
        #pragma unroll
        for (int e = 0; e < 8; e++)
            s0[swz(8*j + e, lane)] = cmul(tw[e*j], y[e]);
    }
    __syncthreads();

    // stage m=8
    {
        const int k  = j & 7;
        const int jm = j - k;
        #pragma unroll
        for (int f = 0; f < 8; f++) av[f] = s0[swz(j + 64*f, lane)];
        bfly8<false>(av, y);
        #pragma unroll
        for (int e = 0; e < 8; e++)
            s1[swz(8*jm + k + 8*e, lane)] = cmul(tw[e*jm], y[e]);
    }
    __syncthreads();

    // stage m=64 fused with full store
    {
        #pragma unroll
        for (int f = 0; f < 8; f++) av[f] = s1[swz(j + 64*f, lane)];
        bfly8<false>(av, y);
        float2* __restrict__ gout = g_bufB + img * N2 + col0 + lane;
        #pragma unroll
        for (int e = 0; e < 8; e++) gout[(j + 64*e)*N1] = y[e];
    }
}

// ---------------------------------------------------------------------------
// Kernel 4: inverse column FFT (B -> A). Full load; store only rows
// [128,384) (e in {2..5}).
// ---------------------------------------------------------------------------
__global__ void __launch_bounds__(256) k_col8_inv()
{
    __shared__ float2 s0[2048], s1[2048];
    __shared__ float2 tw[512];
    const int t    = threadIdx.x;
    const int lane = t & 3;
    const int j    = t >> 2;
    const int img  = blockIdx.x >> 7;
    const int col0 = (blockIdx.x & 127) * 4;

    fill_tw<true>(tw, t);
    __syncthreads();

    float2 av[8], y[8];
    const float2* __restrict__ gin = g_bufB + img * N2 + col0 + lane;

    // stage m=1 fused with full load
    {
        #pragma unroll
        for (int f = 0; f < 8; f++) av[f] = gin[(j + 64*f)*N1];
        bfly8<true>(av, y);
        #pragma unroll
        for (int e = 0; e < 8; e++)
            s0[swz(8*j + e, lane)] = cmul(tw[e*j], y[e]);
    }
    __syncthreads();

    // stage m=8
    {
        const int k  = j & 7;
        const int jm = j - k;
        #pragma unroll
        for (int f = 0; f < 8; f++) av[f] = s0[swz(j + 64*f, lane)];
        bfly8<true>(av, y);
        #pragma unroll
        for (int e = 0; e < 8; e++)
            s1[swz(8*jm + k + 8*e, lane)] = cmul(tw[e*jm], y[e]);
    }
    __syncthreads();

    // stage m=64 fused with half store (rows 128..383)
    {
        #pragma unroll
        for (int f = 0; f < 8; f++) av[f] = s1[swz(j + 64*f, lane)];
        bfly8<true>(av, y);
        float2* __restrict__ gout = g_bufA + img * N2 + col0 + lane;
        #pragma unroll
        for (int e = 2; e <= 5; e++) gout[(j + 64*e)*N1] = y[e];
    }
}

// ---------------------------------------------------------------------------
// Kernel 3: frequency mixing, IN PLACE on g_bufB (unchanged, verified).
// ---------------------------------------------------------------------------
__global__ void __launch_bounds__(256) k_combine(
    const float* __restrict__ kr, const float* __restrict__ ki, int sk)
{
    const int hw = blockIdx.x * 256 + threadIdx.x;
    float2 K[NA*NA];
    #pragma unroll
    for (int i = 0; i < NA*NA; i++) {
        int idx = clampi(i*N2 + hw, NK);
        K[i] = make_float2(kr[sk*idx], ki[sk*idx]);
    }

    for (int c = 0; c < NC; c++) {
        float2 fx[NA];
        #pragma unroll
        for (int ai = 0; ai < NA; ai++)
            fx[ai] = g_bufB[clampi((c*NA + ai)*N2 + hw, CAPG)];
        #pragma unroll
        for (int ao = 0; ao < NA; ao++) {
            float2 yv = make_float2(0.f, 0.f);
            #pragma unroll
            for (int ai = 0; ai < NA; ai++) {
                float2 kk = K[ao*NA + ai];
                float2 f  = fx[ai];
                yv.x += f.x*kk.x - f.y*kk.y;
                yv.y += f.x*kk.y + f.y*kk.x;
            }
            g_bufB[clampi((c*NA + ao)*N2 + hw, CAPG)] = yv;
        }
    }
}

// ---------------------------------------------------------------------------
// Kernel 5: inverse row FFT + crop + scale. Radix-8, 4 rows/block.
// Full load of g_bufA rows [128,384); store only padded cols [128,384)
// cropped to [0,256), scaled by 4/512^2.
// ---------------------------------------------------------------------------
__global__ void __launch_bounds__(256) k_row_inv8()
{
    __shared__ float2 s0[2048], s1[2048];
    __shared__ float2 tw[512];
    const int t    = threadIdx.x;
    const int lane = t & 3;
    const int j    = t >> 2;
    const int img  = blockIdx.x >> 6;
    const int h    = (blockIdx.x & 63) * 4 + lane;

    fill_tw<true>(tw, t);
    __syncthreads();

    float2 av[8], y[8];
    const float2* __restrict__ gin = g_bufA + img * N2 + (128 + h) * N1;

    // stage m=1 fused with full load
    {
        #pragma unroll
        for (int f = 0; f < 8; f++) av[f] = gin[j + 64*f];
        bfly8<true>(av, y);
        #pragma unroll
        for (int e = 0; e < 8; e++)
            s0[swz(8*j + e, lane)] = cmul(tw[e*j], y[e]);
    }
    __syncthreads();

    // stage m=8
    {
        const int k  = j & 7;
        const int jm = j - k;
        #pragma unroll
        for (int f = 0; f < 8; f++) av[f] = s0[swz(j + 64*f, lane)];
        bfly8<true>(av, y);
        #pragma unroll
        for (int e = 0; e < 8; e++)
            s1[swz(8*jm + k + 8*e, lane)] = cmul(tw[e*jm], y[e]);
    }
    __syncthreads();

    // stage m=64 fused with crop+scale store (padded cols 128..383)
    {
        #pragma unroll
        for (int f = 0; f < 8; f++) av[f] = s1[swz(j + 64*f, lane)];
        bfly8<true>(av, y);
        const float scale = 4.0f / (512.0f * 512.0f);
        float2* __restrict__ gout = g_bufB + img * HH*WW + h * WW;
        #pragma unroll
        for (int e = 2; e <= 5; e++) {
            int cc = j + 64*e - 128;       // 0..255
            gout[cc] = make_float2(y[e].x * scale, y[e].y * scale);
        }
    }
}

// ---------------------------------------------------------------------------
// Kernel 6: coil combine, PLANAR float32 output (unchanged, verified).
// ---------------------------------------------------------------------------
__global__ void __launch_bounds__(256) k_final(
    const float* __restrict__ mr, const float* __restrict__ mi, int sm_,
    float* __restrict__ out, int capf)
{
    const int hw = blockIdx.x * 256 + threadIdx.x;
    float2 acc[NA];
    #pragma unroll
    for (int a = 0; a < NA; a++) acc[a] = make_float2(0.f, 0.f);

    for (int c = 0; c < NC; c++) {
        int im = clampi(c*HH*WW + hw, NM);
        float2 m = make_float2(mr[sm_*im], mi[sm_*im]);
        #pragma unroll
        for (int a = 0; a < NA; a++) {
            float2 yv = g_bufB[clampi((c*NA + a)*HH*WW + hw, CAPG)];
            acc[a].x += m.x*yv.x + m.y*yv.y;   // conj(m) * y
            acc[a].y += m.x*yv.y - m.y*yv.x;
        }
    }
    #pragma unroll
    for (int a = 0; a < NA; a++) {
        int idx = a*HH*WW + hw;
        if (idx < capf)      out[idx]      = acc[a].x;
        if (NX + idx < capf) out[NX + idx] = acc[a].y;
    }
}

// ---------------------------------------------------------------------------
extern "C" void kernel_launch(void* const* d_in, const int* in_sizes, int n_in,
                              void* d_out, int out_size)
{
    // Confirmed model (R13/R14 PASSED): dict-order inputs (x_r, x_i, mps_r,
    // mps_i, kern_r, kern_i), real first within each size family; sizes as
    // elements (E) or bytes (4E); PLANAR [2,A,H,W] float32 output.
    const float *xr = 0, *xi = 0, *mr = 0, *mi = 0, *kr = 0, *ki = 0;
    int sx = 1, sm_ = 1, sk = 1;

    if (n_in >= 6) {
        for (int i = 0; i < n_in; i++) {
            const float* p = (const float*)d_in[i];
            const long long sz = in_sizes[i];
            if (sz == NX || sz == 4LL*NX)      { if (!xr) xr = p; else if (!xi) xi = p; }
            else if (sz == NM || sz == 4LL*NM) { if (!mr) mr = p; else if (!mi) mi = p; }
            else if (sz == NK || sz == 4LL*NK) { if (!kr) kr = p; else if (!ki) ki = p; }
        }
        if (!xr || !xi || !mr || !mi || !kr || !ki) {
            xr = (const float*)d_in[0]; xi = (const float*)d_in[1];
            mr = (const float*)d_in[2]; mi = (const float*)d_in[3];
            kr = (const float*)d_in[4]; ki = (const float*)d_in[5];
        }
    } else if (n_in >= 3) {
        for (int i = 0; i < 3; i++) {
            const float* p = (const float*)d_in[i];
            const long long sz = in_sizes[i];
            if (sz == NX || sz == 2LL*NX || sz == 8LL*NX)      { xr = p; xi = p + 1; sx = 2; }
            else if (sz == NM || sz == 2LL*NM || sz == 8LL*NM) { mr = p; mi = p + 1; sm_ = 2; }
            else if (sz == NK || sz == 2LL*NK || sz == 8LL*NK) { kr = p; ki = p + 1; sk = 2; }
        }
        if (!xr || !mr || !kr) { return; }
    } else {
        return;
    }

    int capf = (out_size >= 2*NX) ? 2*NX : out_size;

    // 1. modulate + pad + forward row FFT        (-> A rows 128..383)
    k_row_fwd8<<<NIMG * 64, 256>>>(xr, xi, sx, mr, mi, sm_);
    // 2. forward column FFT                      (A -> B, full)
    k_col8_fwd<<<NIMG * 128, 256>>>();
    // 3. frequency-domain kernel mixing          (B in place)
    k_combine<<<N2 / 256, 256>>>(kr, ki, sk);
    // 4. inverse column FFT                      (B -> A rows 128..383)
    k_col8_inv<<<NIMG * 128, 256>>>();
    // 5. inverse row FFT + crop + scale          (A -> B front region)
    k_row_inv8<<<NIMG * 64, 256>>>();
    // 6. coil combine (PLANAR output)            (B front + mps -> out)
    k_final<<<HH * WW / 256, 256>>>(mr, mi, sm_, (float*)d_out, capf);
}